// round 4
// baseline (speedup 1.0000x reference)
#include <cuda_runtime.h>

#define NB 16
#define CH 256
#define KS 6
#define MS 22
#define HO 17
#define OUT_PER_N (HO*HO)          // 289
#define TOT_OUT (NB*OUT_PER_N)     // 4624
#define CPB 16                     // channels per block
#define NCHUNK (CH/CPB)            // 16
#define RS 23                      // padded smem row stride (23 odd -> near conflict-free)
#define CSTR (MS*RS)               // 506 floats per channel tile
#define TPB 272                    // 17 oy * 16 cl
#define OXW 9                      // outputs per thread (half 0: 9, half 1: 8)
#define XCOLS 14                   // x columns per row needed per half

// scratch: transposed partials, 16B-aligned for float4 epilogue reads
__device__ float4 g_pT4[TOT_OUT * 4];   // [idx][16 chunks] as 4 float4

__device__ __forceinline__ float fsqrt_fast(float a) {
    float r; asm("sqrt.approx.f32 %0, %1;" : "=f"(r) : "f"(a)); return r;
}

// ---------------------------------------------------------------------------
// Kernel 1: per-(n, 16-channel chunk, ox-half) sliding-window correlation.
// thread = (oy, channel lane); 9 (or 8) sliding outputs per thread.
// ---------------------------------------------------------------------------
__global__ __launch_bounds__(TPB) void corr_kernel(
    const float* __restrict__ z, const float* __restrict__ x,
    const float* __restrict__ w)
{
    __shared__ float xs[CPB * CSTR];      // 8096 floats; reused as reduce scratch
    __shared__ float zs[CPB * KS * KS];   // 576 floats

    const int chunk = blockIdx.x;
    const int n     = blockIdx.y;
    const int half  = blockIdx.z;
    const int ox0   = half * OXW;         // 0 or 9
    const int t     = threadIdx.x;

    // --- x load: float4 gmem, fused sqrt, padded smem store ---
    // 16 ch * 484 floats = 1936 float4. One magic-div set per 4 elements.
    const float4* xg4 = (const float4*)(x + (size_t)(n * CH + chunk * CPB) * (MS * MS));
    for (int e4 = t; e4 < CPB * 121; e4 += TPB) {
        float4 v = xg4[e4];
        unsigned cl   = (unsigned)e4 / 121u;
        unsigned rem4 = (unsigned)e4 - cl * 121u;
        unsigned fb   = 4u * rem4;                // 0..480
        unsigned r0   = fb / 22u;
        unsigned c0   = fb - r0 * 22u;
        unsigned base = cl * CSTR + r0 * RS + c0;
        // row-wrap correction: pad width is 1, so wrapping adds exactly +1
        xs[base + 0 + (c0 + 0 >= 22u ? 1u : 0u)] = fsqrt_fast(v.x);
        xs[base + 1 + (c0 + 1 >= 22u ? 1u : 0u)] = fsqrt_fast(v.y);
        xs[base + 2 + (c0 + 2 >= 22u ? 1u : 0u)] = fsqrt_fast(v.z);
        xs[base + 3 + (c0 + 3 >= 22u ? 1u : 0u)] = fsqrt_fast(v.w);
    }
    // --- z load (tiny) ---
    const float* zg = z + (size_t)(n * CH + chunk * CPB) * (KS * KS);
    for (int e = t; e < CPB * KS * KS; e += TPB) {
        unsigned cl = (unsigned)e / 36u;
        zs[e] = fsqrt_fast(zg[e]) * w[chunk * CPB + cl];
    }
    __syncthreads();

    // --- compute: thread = (oy, cl), slide over 9 ox positions ---
    const int oy = t % HO;
    const int cl = t / HO;
    const float* xb = &xs[cl * CSTR + ox0];
    const float* zb = &zs[cl * KS * KS];

    float acc[OXW];
#pragma unroll
    for (int i = 0; i < OXW; i++) acc[i] = 0.f;

#pragma unroll
    for (int k1 = 0; k1 < KS; k1++) {
        float xr[XCOLS];
#pragma unroll
        for (int j = 0; j < XCOLS; j++) xr[j] = xb[(oy + k1) * RS + j];
#pragma unroll
        for (int k2 = 0; k2 < KS; k2++) {
            float zv = zb[k1 * KS + k2];
#pragma unroll
            for (int i = 0; i < OXW; i++)
                acc[i] = fmaf(xr[i + k2], zv, acc[i]);
        }
    }

    // --- block reduce over 16 channel lanes (fixed order) ---
    __syncthreads();
    float* scratch = xs;                  // 16 * 153 floats, fits easily
#pragma unroll
    for (int i = 0; i < OXW; i++)
        scratch[cl * (HO * OXW) + oy * OXW + i] = acc[i];
    __syncthreads();

    float* gp = (float*)g_pT4;
    for (int idx = t; idx < HO * OXW; idx += TPB) {
        int oyo = idx / OXW;
        int i   = idx - oyo * OXW;
        if (half == 1 && i == OXW - 1) continue;   // half 1 has only 8 valid ox
        float s = 0.f;
#pragma unroll
        for (int c2 = 0; c2 < CPB; c2++) s += scratch[c2 * (HO * OXW) + idx];
        int gidx = n * OUT_PER_N + oyo * HO + ox0 + i;
        gp[gidx * 16 + chunk] = s;
    }
}

// ---------------------------------------------------------------------------
// Kernel 2: chunk reduce (float4 over transposed partials) + global BN.
// ---------------------------------------------------------------------------
#define BNT 1024
#define VPT 5                              // 1024*5 >= 4624
__global__ __launch_bounds__(BNT) void reduce_bn(
    float* __restrict__ out,
    const float* __restrict__ bw, const float* __restrict__ bb)
{
    __shared__ float sred[BNT];
    __shared__ float s_mu, s_scale;
    const int t = threadIdx.x;

    float v[VPT];
    float lsum = 0.f;
#pragma unroll
    for (int k = 0; k < VPT; k++) {
        int idx = t + k * BNT;
        float s = 0.f;
        if (idx < TOT_OUT) {
            float4 a = g_pT4[idx * 4 + 0];
            float4 b = g_pT4[idx * 4 + 1];
            float4 c = g_pT4[idx * 4 + 2];
            float4 d = g_pT4[idx * 4 + 3];
            s = ((a.x + a.y) + (a.z + a.w)) + ((b.x + b.y) + (b.z + b.w))
              + ((c.x + c.y) + (c.z + c.w)) + ((d.x + d.y) + (d.z + d.w));
            s *= (1.f / (KS * KS));
        }
        v[k] = s;
        lsum += s;
    }

    sred[t] = lsum; __syncthreads();
    for (int s = BNT / 2; s > 0; s >>= 1) { if (t < s) sred[t] += sred[t + s]; __syncthreads(); }
    if (t == 0) s_mu = sred[0] / (float)TOT_OUT;
    __syncthreads();
    const float mu = s_mu;

    float lss = 0.f;
#pragma unroll
    for (int k = 0; k < VPT; k++) {
        int idx = t + k * BNT;
        if (idx < TOT_OUT) { float d = v[k] - mu; lss += d * d; }
    }
    sred[t] = lss; __syncthreads();
    for (int s = BNT / 2; s > 0; s >>= 1) { if (t < s) sred[t] += sred[t + s]; __syncthreads(); }
    if (t == 0) s_scale = rsqrtf(sred[0] / (float)TOT_OUT + 1e-5f) * bw[0];
    __syncthreads();
    const float scale = s_scale;
    const float bias  = bb[0];

#pragma unroll
    for (int k = 0; k < VPT; k++) {
        int idx = t + k * BNT;
        if (idx < TOT_OUT) out[idx] = (v[k] - mu) * scale + bias;
    }
}

extern "C" void kernel_launch(void* const* d_in, const int* in_sizes, int n_in,
                              void* d_out, int out_size)
{
    const float* z  = (const float*)d_in[0];
    const float* x  = (const float*)d_in[1];
    const float* w  = (const float*)d_in[2];
    const float* bw = (const float*)d_in[3];
    const float* bb = (const float*)d_in[4];

    int first_one = -1;
    for (int i = 0; i < n_in; i++) {
        if (in_sizes[i] == NB * CH * KS * KS)      z = (const float*)d_in[i];
        else if (in_sizes[i] == NB * CH * MS * MS) x = (const float*)d_in[i];
        else if (in_sizes[i] == CH)                w = (const float*)d_in[i];
        else if (in_sizes[i] == 1) {
            if (first_one < 0) { bw = (const float*)d_in[i]; first_one = i; }
            else                 bb = (const float*)d_in[i];
        }
    }

    dim3 grid(NCHUNK, NB, 2);                    // 512 blocks
    corr_kernel<<<grid, TPB>>>(z, x, w);
    reduce_bn<<<1, BNT>>>((float*)d_out, bw, bb);
}